// round 6
// baseline (speedup 1.0000x reference)
#include <cuda_runtime.h>
#include <cstdint>
#include <cstddef>

#define T_SEQ   12
#define BATCH   2048
#define IN_DIM  512
#define HIDDEN  1024

// ---------------- scratch (no runtime allocation allowed) ----------------
__device__ float d_H [BATCH * HIDDEN];                       // 8 MB  current hidden state
__device__ float d_RH[BATCH * HIDDEN];                       // 8 MB  r * h
__device__ float d_U [BATCH * HIDDEN];                       // 8 MB  update gate
__device__ float d_Gx[(size_t)BATCH * T_SEQ * 2 * HIDDEN];   // 201 MB x@Wg_x + bg
__device__ float d_Cx[(size_t)BATCH * T_SEQ * HIDDEN];       // 100 MB x@Wc_x + bc

// ---------------- tf32 helpers ----------------
__device__ __forceinline__ uint32_t f2tf32(float f) {
    uint32_t u;
    asm("cvt.rna.tf32.f32 %0, %1;" : "=r"(u) : "f"(f));
    return u;
}

__device__ __forceinline__ void mma_tf32(float c[4], const uint32_t a[4], const uint32_t b[2]) {
    asm volatile(
        "mma.sync.aligned.m16n8k8.row.col.f32.tf32.tf32.f32 "
        "{%0,%1,%2,%3}, {%4,%5,%6,%7}, {%8,%9}, {%0,%1,%2,%3};\n"
        : "+f"(c[0]), "+f"(c[1]), "+f"(c[2]), "+f"(c[3])
        : "r"(a[0]), "r"(a[1]), "r"(a[2]), "r"(a[3]), "r"(b[0]), "r"(b[1]));
}

// ---------------- shared GEMM core: 128x128 block tile, BK=32, 256 threads ----------------
// Warp layout: 8 warps as 2 (M) x 4 (N); warp tile 64x32; 4x4 m16n8k8 mma tiles.
#define BM 128
#define BN 128
#define BK 32
#define SA_STRIDE 36   // BK + 4  -> conflict-free A fragment loads
#define SB_STRIDE 136  // BN + 8  -> conflict-free B fragment loads

__device__ __forceinline__ void gemm_core(
    const float* __restrict__ A, int lda,
    const float* __restrict__ B, int ldb,
    int K, int block_row, int block_col,
    float acc[4][4][4])
{
    __shared__ uint32_t sA[BM * SA_STRIDE];
    __shared__ uint32_t sB[BK * SB_STRIDE];

    const int tid  = threadIdx.x;
    const int lane = tid & 31;
    const int warp = tid >> 5;
    const int wm   = warp & 1;   // 0..1 (M)
    const int wn   = warp >> 1;  // 0..3 (N)

#pragma unroll
    for (int mi = 0; mi < 4; mi++)
#pragma unroll
        for (int ni = 0; ni < 4; ni++)
#pragma unroll
            for (int r = 0; r < 4; r++) acc[mi][ni][r] = 0.0f;

    for (int k0 = 0; k0 < K; k0 += BK) {
        // ---- load A tile: 128 x 32 floats (1024 float4, 4 per thread) ----
#pragma unroll
        for (int i = 0; i < 4; i++) {
            int idx = tid + i * 256;
            int r = idx >> 3;
            int c = (idx & 7) << 2;
            float4 v = *(const float4*)(A + (size_t)(block_row + r) * lda + k0 + c);
            uint32_t* dst = sA + r * SA_STRIDE + c;
            dst[0] = f2tf32(v.x); dst[1] = f2tf32(v.y);
            dst[2] = f2tf32(v.z); dst[3] = f2tf32(v.w);
        }
        // ---- load B tile: 32 x 128 floats ----
#pragma unroll
        for (int i = 0; i < 4; i++) {
            int idx = tid + i * 256;
            int r = idx >> 5;
            int c = (idx & 31) << 2;
            float4 v = *(const float4*)(B + (size_t)(k0 + r) * ldb + block_col + c);
            uint32_t* dst = sB + r * SB_STRIDE + c;
            dst[0] = f2tf32(v.x); dst[1] = f2tf32(v.y);
            dst[2] = f2tf32(v.z); dst[3] = f2tf32(v.w);
        }
        __syncthreads();

#pragma unroll
        for (int ks = 0; ks < 4; ks++) {
            const int kk = ks * 8;
            uint32_t af[4][4], bf[4][2];
#pragma unroll
            for (int mi = 0; mi < 4; mi++) {
                int rb = wm * 64 + mi * 16 + (lane >> 2);
                const uint32_t* p = sA + rb * SA_STRIDE + kk + (lane & 3);
                af[mi][0] = p[0];
                af[mi][1] = p[8 * SA_STRIDE];
                af[mi][2] = p[4];
                af[mi][3] = p[8 * SA_STRIDE + 4];
            }
#pragma unroll
            for (int ni = 0; ni < 4; ni++) {
                int cb = wn * 32 + ni * 8 + (lane >> 2);
                const uint32_t* p = sB + (kk + (lane & 3)) * SB_STRIDE + cb;
                bf[ni][0] = p[0];
                bf[ni][1] = p[4 * SB_STRIDE];
            }
#pragma unroll
            for (int mi = 0; mi < 4; mi++)
#pragma unroll
                for (int ni = 0; ni < 4; ni++)
                    mma_tf32(acc[mi][ni], af[mi], bf[ni]);
        }
        __syncthreads();
    }
}

// Output coordinate helper (per mma tile): two rows {row, row+8}, two cols {col, col+1}
#define EPI_COORDS()                                          \
    const int lane = threadIdx.x & 31;                        \
    const int warp = threadIdx.x >> 5;                        \
    const int wm = warp & 1, wn = warp >> 1;                  \
    const int block_row = blockIdx.y * BM;                    \
    const int block_col = blockIdx.x * BN;

__device__ __forceinline__ float sigmoidf_(float x) { return 1.0f / (1.0f + expf(-x)); }

// ---------------- kernel: h <- coded_cords ----------------
__global__ __launch_bounds__(256) void init_h_kernel(const float* __restrict__ src) {
    size_t i = (size_t)blockIdx.x * 256 + threadIdx.x;
    ((float4*)d_H)[i] = ((const float4*)src)[i];
}

// ---------------- kernel: Gx = X @ Wg[0:512,:] + bg  (M=B*T, N=2H, K=D) ----------------
__global__ __launch_bounds__(256) void pre_gate_kernel(
    const float* __restrict__ x, const float* __restrict__ Wg, const float* __restrict__ bg)
{
    float acc[4][4][4];
    EPI_COORDS();
    gemm_core(x, IN_DIM, Wg, 2 * HIDDEN, IN_DIM, block_row, block_col, acc);
#pragma unroll
    for (int mi = 0; mi < 4; mi++)
#pragma unroll
        for (int ni = 0; ni < 4; ni++) {
            int row = block_row + wm * 64 + mi * 16 + (lane >> 2);
            int col = block_col + wn * 32 + ni * 8 + ((lane & 3) << 1);
            float b0 = bg[col], b1 = bg[col + 1];
            float2 v0 = make_float2(acc[mi][ni][0] + b0, acc[mi][ni][1] + b1);
            float2 v1 = make_float2(acc[mi][ni][2] + b0, acc[mi][ni][3] + b1);
            *(float2*)&d_Gx[(size_t)row * (2 * HIDDEN) + col]       = v0;
            *(float2*)&d_Gx[(size_t)(row + 8) * (2 * HIDDEN) + col] = v1;
        }
}

// ---------------- kernel: Cx = X @ Wc[0:512,:] + bc  (M=B*T, N=H, K=D) ----------------
__global__ __launch_bounds__(256) void pre_cand_kernel(
    const float* __restrict__ x, const float* __restrict__ Wc, const float* __restrict__ bc)
{
    float acc[4][4][4];
    EPI_COORDS();
    gemm_core(x, IN_DIM, Wc, HIDDEN, IN_DIM, block_row, block_col, acc);
#pragma unroll
    for (int mi = 0; mi < 4; mi++)
#pragma unroll
        for (int ni = 0; ni < 4; ni++) {
            int row = block_row + wm * 64 + mi * 16 + (lane >> 2);
            int col = block_col + wn * 32 + ni * 8 + ((lane & 3) << 1);
            float b0 = bc[col], b1 = bc[col + 1];
            float2 v0 = make_float2(acc[mi][ni][0] + b0, acc[mi][ni][1] + b1);
            float2 v1 = make_float2(acc[mi][ni][2] + b0, acc[mi][ni][3] + b1);
            *(float2*)&d_Cx[(size_t)row * HIDDEN + col]       = v0;
            *(float2*)&d_Cx[(size_t)(row + 8) * HIDDEN + col] = v1;
        }
}

// ---------------- kernel: gate step: sigmoid(Gx_t + H @ Wg[512:,:]) -> RH, U ----------------
__global__ __launch_bounds__(256) void gate_step_kernel(const float* __restrict__ Wg, int t)
{
    float acc[4][4][4];
    EPI_COORDS();
    gemm_core(d_H, HIDDEN, Wg + (size_t)IN_DIM * 2 * HIDDEN, 2 * HIDDEN, HIDDEN,
              block_row, block_col, acc);
#pragma unroll
    for (int mi = 0; mi < 4; mi++)
#pragma unroll
        for (int ni = 0; ni < 4; ni++) {
            int row0 = block_row + wm * 64 + mi * 16 + (lane >> 2);
            int col  = block_col + wn * 32 + ni * 8 + ((lane & 3) << 1);
#pragma unroll
            for (int r = 0; r < 4; r++) {
                int row = row0 + (r >> 1) * 8;
                int c   = col + (r & 1);
                float g = sigmoidf_(acc[mi][ni][r] +
                                    d_Gx[(size_t)(row * T_SEQ + t) * (2 * HIDDEN) + c]);
                if (c < HIDDEN)
                    d_RH[(size_t)row * HIDDEN + c] = g * d_H[(size_t)row * HIDDEN + c];
                else
                    d_U[(size_t)row * HIDDEN + (c - HIDDEN)] = g;
            }
        }
}

// ---------------- kernel: cand step: c=tanh(Cx_t + RH @ Wc[512:,:]); h=u*h+(1-u)*c ----------------
__global__ __launch_bounds__(256) void cand_step_kernel(
    const float* __restrict__ Wc, float* __restrict__ y, int t)
{
    float acc[4][4][4];
    EPI_COORDS();
    gemm_core(d_RH, HIDDEN, Wc + (size_t)IN_DIM * HIDDEN, HIDDEN, HIDDEN,
              block_row, block_col, acc);
#pragma unroll
    for (int mi = 0; mi < 4; mi++)
#pragma unroll
        for (int ni = 0; ni < 4; ni++) {
            int row0 = block_row + wm * 64 + mi * 16 + (lane >> 2);
            int col  = block_col + wn * 32 + ni * 8 + ((lane & 3) << 1);
#pragma unroll
            for (int r = 0; r < 4; r++) {
                int row = row0 + (r >> 1) * 8;
                int c   = col + (r & 1);
                size_t hi = (size_t)row * HIDDEN + c;
                float cc = tanhf(acc[mi][ni][r] +
                                 d_Cx[(size_t)(row * T_SEQ + t) * HIDDEN + c]);
                float u = d_U[hi];
                float h = d_H[hi];
                float hn = u * h + (1.0f - u) * cc;
                d_H[hi] = hn;
                y[(size_t)row * T_SEQ * HIDDEN + (size_t)t * HIDDEN + c] = hn;
            }
        }
}

// ---------------- launch ----------------
extern "C" void kernel_launch(void* const* d_in, const int* in_sizes, int n_in,
                              void* d_out, int out_size)
{
    const float* x  = (const float*)d_in[0];  // [B, T, D]
    const float* h0 = (const float*)d_in[1];  // [B, H]
    const float* Wg = (const float*)d_in[2];  // [D+H, 2H]
    const float* bg = (const float*)d_in[3];  // [2H]
    const float* Wc = (const float*)d_in[4];  // [D+H, H]
    const float* bc = (const float*)d_in[5];  // [H]
    float* y = (float*)d_out;                 // [B, T, H]

    // h <- coded_cords
    init_h_kernel<<<(BATCH * HIDDEN / 4) / 256, 256>>>(h0);

    // Precompute x-dependent halves (fully parallel over B*T)
    {
        dim3 g(2 * HIDDEN / BN, (BATCH * T_SEQ) / BM);   // (16, 192)
        pre_gate_kernel<<<g, 256>>>(x, Wg, bg);
    }
    {
        dim3 g(HIDDEN / BN, (BATCH * T_SEQ) / BM);       // (8, 192)
        pre_cand_kernel<<<g, 256>>>(x, Wc, bc);
    }

    // Serial recurrence
    for (int t = 0; t < T_SEQ; t++) {
        dim3 gg(2 * HIDDEN / BN, BATCH / BM);            // (16, 16)
        gate_step_kernel<<<gg, 256>>>(Wg, t);
        dim3 gc(HIDDEN / BN, BATCH / BM);                // (8, 16)
        cand_step_kernel<<<gc, 256>>>(Wc, y, t);
    }
}

// round 7
// speedup vs baseline: 1.2423x; 1.2423x over previous
#include <cuda_runtime.h>
#include <cstdint>
#include <cstddef>

#define T_SEQ   12
#define BATCH   2048
#define IN_DIM  512
#define HIDDEN  1024

// ---------------- scratch (no runtime allocation allowed) ----------------
__device__ float d_H [BATCH * HIDDEN];                       // current hidden state
__device__ float d_RH[BATCH * HIDDEN];                       // r * h
__device__ float d_U [BATCH * HIDDEN];                       // update gate
__device__ float d_Gx[(size_t)BATCH * T_SEQ * 2 * HIDDEN];   // x@Wg_x + bg
__device__ float d_Cx[(size_t)BATCH * T_SEQ * HIDDEN];       // x@Wc_x + bc

// ---------------- mma / cp.async helpers ----------------
__device__ __forceinline__ void mma_tf32(float c[4], const uint32_t a[4], const uint32_t b[2]) {
    asm volatile(
        "mma.sync.aligned.m16n8k8.row.col.f32.tf32.tf32.f32 "
        "{%0,%1,%2,%3}, {%4,%5,%6,%7}, {%8,%9}, {%0,%1,%2,%3};\n"
        : "+f"(c[0]), "+f"(c[1]), "+f"(c[2]), "+f"(c[3])
        : "r"(a[0]), "r"(a[1]), "r"(a[2]), "r"(a[3]), "r"(b[0]), "r"(b[1]));
}

__device__ __forceinline__ void cp_async16(uint32_t dst, const void* src) {
    asm volatile("cp.async.cg.shared.global [%0], [%1], 16;\n" :: "r"(dst), "l"(src));
}

// ---------------- shared GEMM core: 128x128 block tile, BK=32, 256 threads ----------------
// Warp layout: 8 warps as 2 (M) x 4 (N); warp tile 64x32; 4x4 m16n8k8 mma tiles.
// Double-buffered dynamic smem, cp.async pipeline; raw fp32 bits fed to tf32 MMA
// (hardware mantissa truncation; no explicit cvt).
#define BM 128
#define BN 128
#define BK 32
#define SA_STRIDE 36   // BK + 4  (144 B, 16B-aligned) -> conflict-free A fragment loads
#define SB_STRIDE 136  // BN + 8  (544 B, 16B-aligned) -> conflict-free B fragment loads
#define SA_ELEMS  (BM * SA_STRIDE)
#define SB_ELEMS  (BK * SB_STRIDE)
#define SMEM_BYTES ((2 * SA_ELEMS + 2 * SB_ELEMS) * 4)   // 71680

__device__ __forceinline__ void load_stage(
    uint32_t sA_addr, uint32_t sB_addr,
    const float* __restrict__ A, int lda,
    const float* __restrict__ B, int ldb,
    int block_row, int block_col, int k0, int tid)
{
#pragma unroll
    for (int i = 0; i < 4; i++) {
        int idx = tid + i * 256;
        int r = idx >> 3, c = (idx & 7) << 2;
        cp_async16(sA_addr + (uint32_t)(r * SA_STRIDE + c) * 4,
                   A + (size_t)(block_row + r) * lda + k0 + c);
    }
#pragma unroll
    for (int i = 0; i < 4; i++) {
        int idx = tid + i * 256;
        int r = idx >> 5, c = (idx & 31) << 2;
        cp_async16(sB_addr + (uint32_t)(r * SB_STRIDE + c) * 4,
                   B + (size_t)(k0 + r) * ldb + block_col + c);
    }
    asm volatile("cp.async.commit_group;\n" ::: "memory");
}

__device__ __forceinline__ void gemm_core(
    const float* __restrict__ A, int lda,
    const float* __restrict__ B, int ldb,
    int K, int block_row, int block_col,
    float acc[4][4][4])
{
    extern __shared__ uint32_t smem[];
    uint32_t* sA = smem;                     // [2][SA_ELEMS]
    uint32_t* sB = smem + 2 * SA_ELEMS;      // [2][SB_ELEMS]

    const int tid  = threadIdx.x;
    const int lane = tid & 31;
    const int warp = tid >> 5;
    const int wm   = warp & 1;   // 0..1 (M)
    const int wn   = warp >> 1;  // 0..3 (N)

    const uint32_t sA_base = (uint32_t)__cvta_generic_to_shared(sA);
    const uint32_t sB_base = (uint32_t)__cvta_generic_to_shared(sB);

#pragma unroll
    for (int mi = 0; mi < 4; mi++)
#pragma unroll
        for (int ni = 0; ni < 4; ni++)
#pragma unroll
            for (int r = 0; r < 4; r++) acc[mi][ni][r] = 0.0f;

    const int nsteps = K / BK;

    // prologue: stage 0 in flight
    load_stage(sA_base, sB_base, A, lda, B, ldb, block_row, block_col, 0, tid);

    for (int s = 0; s < nsteps; s++) {
        const int cur = s & 1;
        if (s + 1 < nsteps) {
            const int nxt = (s + 1) & 1;
            load_stage(sA_base + (uint32_t)nxt * SA_ELEMS * 4,
                       sB_base + (uint32_t)nxt * SB_ELEMS * 4,
                       A, lda, B, ldb, block_row, block_col, (s + 1) * BK, tid);
            asm volatile("cp.async.wait_group 1;\n" ::: "memory");
        } else {
            asm volatile("cp.async.wait_group 0;\n" ::: "memory");
        }
        __syncthreads();

        const uint32_t* cA = sA + (size_t)cur * SA_ELEMS;
        const uint32_t* cB = sB + (size_t)cur * SB_ELEMS;

#pragma unroll
        for (int ks = 0; ks < 4; ks++) {
            const int kk = ks * 8;
            uint32_t af[4][4], bf[4][2];
#pragma unroll
            for (int mi = 0; mi < 4; mi++) {
                int rb = wm * 64 + mi * 16 + (lane >> 2);
                const uint32_t* p = cA + rb * SA_STRIDE + kk + (lane & 3);
                af[mi][0] = p[0];
                af[mi][1] = p[8 * SA_STRIDE];
                af[mi][2] = p[4];
                af[mi][3] = p[8 * SA_STRIDE + 4];
            }
#pragma unroll
            for (int ni = 0; ni < 4; ni++) {
                int cb = wn * 32 + ni * 8 + (lane >> 2);
                const uint32_t* p = cB + (kk + (lane & 3)) * SB_STRIDE + cb;
                bf[ni][0] = p[0];
                bf[ni][1] = p[4 * SB_STRIDE];
            }
#pragma unroll
            for (int mi = 0; mi < 4; mi++)
#pragma unroll
                for (int ni = 0; ni < 4; ni++)
                    mma_tf32(acc[mi][ni], af[mi], bf[ni]);
        }
        __syncthreads();   // protect cur buffer before it is refilled at s+2
    }
}

// Output coordinate helper
#define EPI_COORDS()                                          \
    const int lane = threadIdx.x & 31;                        \
    const int warp = threadIdx.x >> 5;                        \
    const int wm = warp & 1, wn = warp >> 1;                  \
    const int block_row = blockIdx.y * BM;                    \
    const int block_col = blockIdx.x * BN;

__device__ __forceinline__ float sigmoidf_(float x) { return 1.0f / (1.0f + expf(-x)); }

// ---------------- kernel: h <- coded_cords ----------------
__global__ __launch_bounds__(256) void init_h_kernel(const float* __restrict__ src) {
    size_t i = (size_t)blockIdx.x * 256 + threadIdx.x;
    ((float4*)d_H)[i] = ((const float4*)src)[i];
}

// ---------------- kernel: Gx = X @ Wg[0:512,:] + bg  (M=B*T, N=2H, K=D) ----------------
__global__ __launch_bounds__(256) void pre_gate_kernel(
    const float* __restrict__ x, const float* __restrict__ Wg, const float* __restrict__ bg)
{
    float acc[4][4][4];
    EPI_COORDS();
    gemm_core(x, IN_DIM, Wg, 2 * HIDDEN, IN_DIM, block_row, block_col, acc);
#pragma unroll
    for (int mi = 0; mi < 4; mi++)
#pragma unroll
        for (int ni = 0; ni < 4; ni++) {
            int row = block_row + wm * 64 + mi * 16 + (lane >> 2);
            int col = block_col + wn * 32 + ni * 8 + ((lane & 3) << 1);
            float b0 = bg[col], b1 = bg[col + 1];
            *(float2*)&d_Gx[(size_t)row * (2 * HIDDEN) + col] =
                make_float2(acc[mi][ni][0] + b0, acc[mi][ni][1] + b1);
            *(float2*)&d_Gx[(size_t)(row + 8) * (2 * HIDDEN) + col] =
                make_float2(acc[mi][ni][2] + b0, acc[mi][ni][3] + b1);
        }
}

// ---------------- kernel: Cx = X @ Wc[0:512,:] + bc  (M=B*T, N=H, K=D) ----------------
__global__ __launch_bounds__(256) void pre_cand_kernel(
    const float* __restrict__ x, const float* __restrict__ Wc, const float* __restrict__ bc)
{
    float acc[4][4][4];
    EPI_COORDS();
    gemm_core(x, IN_DIM, Wc, HIDDEN, IN_DIM, block_row, block_col, acc);
#pragma unroll
    for (int mi = 0; mi < 4; mi++)
#pragma unroll
        for (int ni = 0; ni < 4; ni++) {
            int row = block_row + wm * 64 + mi * 16 + (lane >> 2);
            int col = block_col + wn * 32 + ni * 8 + ((lane & 3) << 1);
            float b0 = bc[col], b1 = bc[col + 1];
            *(float2*)&d_Cx[(size_t)row * HIDDEN + col] =
                make_float2(acc[mi][ni][0] + b0, acc[mi][ni][1] + b1);
            *(float2*)&d_Cx[(size_t)(row + 8) * HIDDEN + col] =
                make_float2(acc[mi][ni][2] + b0, acc[mi][ni][3] + b1);
        }
}

// ---------------- kernel: gate step: sigmoid(Gx_t + H @ Wg[512:,:]) -> RH, U ----------------
__global__ __launch_bounds__(256) void gate_step_kernel(const float* __restrict__ Wg, int t)
{
    float acc[4][4][4];
    EPI_COORDS();
    gemm_core(d_H, HIDDEN, Wg + (size_t)IN_DIM * 2 * HIDDEN, 2 * HIDDEN, HIDDEN,
              block_row, block_col, acc);
    const bool is_reset = (block_col < HIDDEN);   // uniform per block (HIDDEN % BN == 0)
#pragma unroll
    for (int mi = 0; mi < 4; mi++)
#pragma unroll
        for (int ni = 0; ni < 4; ni++) {
            int row0 = block_row + wm * 64 + mi * 16 + (lane >> 2);
            int col  = block_col + wn * 32 + ni * 8 + ((lane & 3) << 1);
#pragma unroll
            for (int p = 0; p < 2; p++) {
                int row = row0 + p * 8;
                float2 gx = *(const float2*)&d_Gx[(size_t)(row * T_SEQ + t) * (2 * HIDDEN) + col];
                float g0 = sigmoidf_(acc[mi][ni][2 * p + 0] + gx.x);
                float g1 = sigmoidf_(acc[mi][ni][2 * p + 1] + gx.y);
                if (is_reset) {
                    size_t hi = (size_t)row * HIDDEN + col;
                    float2 h = *(const float2*)&d_H[hi];
                    *(float2*)&d_RH[hi] = make_float2(g0 * h.x, g1 * h.y);
                } else {
                    size_t ui = (size_t)row * HIDDEN + (col - HIDDEN);
                    *(float2*)&d_U[ui] = make_float2(g0, g1);
                }
            }
        }
}

// ---------------- kernel: cand step: c=tanh(Cx_t + RH @ Wc[512:,:]); h=u*h+(1-u)*c ----------------
__global__ __launch_bounds__(256) void cand_step_kernel(
    const float* __restrict__ Wc, float* __restrict__ y, int t)
{
    float acc[4][4][4];
    EPI_COORDS();
    gemm_core(d_RH, HIDDEN, Wc + (size_t)IN_DIM * HIDDEN, HIDDEN, HIDDEN,
              block_row, block_col, acc);
#pragma unroll
    for (int mi = 0; mi < 4; mi++)
#pragma unroll
        for (int ni = 0; ni < 4; ni++) {
            int row0 = block_row + wm * 64 + mi * 16 + (lane >> 2);
            int col  = block_col + wn * 32 + ni * 8 + ((lane & 3) << 1);
#pragma unroll
            for (int p = 0; p < 2; p++) {
                int row = row0 + p * 8;
                size_t hi = (size_t)row * HIDDEN + col;
                float2 cx = *(const float2*)&d_Cx[(size_t)(row * T_SEQ + t) * HIDDEN + col];
                float c0 = tanhf(acc[mi][ni][2 * p + 0] + cx.x);
                float c1 = tanhf(acc[mi][ni][2 * p + 1] + cx.y);
                float2 u = *(const float2*)&d_U[hi];
                float2 h = *(const float2*)&d_H[hi];
                float hn0 = u.x * h.x + (1.0f - u.x) * c0;
                float hn1 = u.y * h.y + (1.0f - u.y) * c1;
                *(float2*)&d_H[hi] = make_float2(hn0, hn1);
                *(float2*)&y[(size_t)row * T_SEQ * HIDDEN + (size_t)t * HIDDEN + col] =
                    make_float2(hn0, hn1);
            }
        }
}

// ---------------- launch ----------------
extern "C" void kernel_launch(void* const* d_in, const int* in_sizes, int n_in,
                              void* d_out, int out_size)
{
    const float* x  = (const float*)d_in[0];  // [B, T, D]
    const float* h0 = (const float*)d_in[1];  // [B, H]
    const float* Wg = (const float*)d_in[2];  // [D+H, 2H]
    const float* bg = (const float*)d_in[3];  // [2H]
    const float* Wc = (const float*)d_in[4];  // [D+H, H]
    const float* bc = (const float*)d_in[5];  // [H]
    float* y = (float*)d_out;                 // [B, T, H]

    // opt-in to >48KB dynamic smem (host-side attribute, idempotent, not a stream op)
    cudaFuncSetAttribute(pre_gate_kernel, cudaFuncAttributeMaxDynamicSharedMemorySize, SMEM_BYTES);
    cudaFuncSetAttribute(pre_cand_kernel, cudaFuncAttributeMaxDynamicSharedMemorySize, SMEM_BYTES);
    cudaFuncSetAttribute(gate_step_kernel, cudaFuncAttributeMaxDynamicSharedMemorySize, SMEM_BYTES);
    cudaFuncSetAttribute(cand_step_kernel, cudaFuncAttributeMaxDynamicSharedMemorySize, SMEM_BYTES);

    // h <- coded_cords
    init_h_kernel<<<(BATCH * HIDDEN / 4) / 256, 256>>>(h0);

    // Precompute x-dependent halves (fully parallel over B*T)
    {
        dim3 g(2 * HIDDEN / BN, (BATCH * T_SEQ) / BM);   // (16, 192)
        pre_gate_kernel<<<g, 256, SMEM_BYTES>>>(x, Wg, bg);
    }
    {
        dim3 g(HIDDEN / BN, (BATCH * T_SEQ) / BM);       // (8, 192)
        pre_cand_kernel<<<g, 256, SMEM_BYTES>>>(x, Wc, bc);
    }

    // Serial recurrence
    for (int t = 0; t < T_SEQ; t++) {
        dim3 gg(2 * HIDDEN / BN, BATCH / BM);            // (16, 16)
        gate_step_kernel<<<gg, 256, SMEM_BYTES>>>(Wg, t);
        dim3 gc(HIDDEN / BN, BATCH / BM);                // (8, 16)
        cand_step_kernel<<<gc, 256, SMEM_BYTES>>>(Wc, y, t);
    }
}